// round 13
// baseline (speedup 1.0000x reference)
#include <cuda_runtime.h>
#include <math.h>
#include <stdint.h>

#define DD 512
#define DH 256                      // d-rows per CTA
#define PP 36
#define PS 37                       // padded row stride, conflict-free
#define NT 512
#define EPSN 1e-12f
#define SCALE_CLS 7.0f

// SMEM float offsets
#define T_OFF   0                   // test half-tile [256][37] = 9472
#define R_OFF   9472                // train half-tile
#define PAR_T   18944               // per-float4 partial sums test [2304]
#define PAR_R   21248               // train [2304]
#define MEAN_T  23552               // [256]
#define MEAN_R  23808               // [256]
#define X_OFF   24064               // my partials [148]: 0..2 stageA, 3..74 n2, 75..146 ta
#define INB1    24212               // peer inbox 1 [148]
#define NRM     24360               // merged norms [72]
#define SCR     24432               // merged scores [72]
#define WWT     24504               // weights [72]
#define RED     24576               // warp scratch [24]
#define X2_OFF  24600               // my stage-D partials [4]
#define INB2    24604               // peer inbox 2 [4]
#define SMEMF   24608
#define SMEMB   (SMEMF*4)           // 98,432 B -> 2 CTAs/SM

__device__ __forceinline__ float warp_sum(float v) {
#pragma unroll
    for (int o = 16; o > 0; o >>= 1) v += __shfl_down_sync(0xffffffffu, v, o);
    return v;
}
__device__ __forceinline__ uint32_t smem_u32(const void* p) {
    uint32_t a;
    asm("{ .reg .u64 t; cvta.to.shared.u64 t, %1; cvt.u32.u64 %0, t; }" : "=r"(a) : "l"(p));
    return a;
}
__device__ __forceinline__ void st_cluster_f32(uint32_t laddr, uint32_t peer, float v) {
    uint32_t r;
    asm volatile("mapa.shared::cluster.u32 %0, %1, %2;" : "=r"(r) : "r"(laddr), "r"(peer));
    asm volatile("st.shared::cluster.f32 [%0], %1;" :: "r"(r), "f"(v) : "memory");
}
#define CLUSTER_SYNC() do { \
    asm volatile("barrier.cluster.arrive.aligned;" ::: "memory"); \
    asm volatile("barrier.cluster.wait.aligned;"   ::: "memory"); \
} while (0)

__global__ __launch_bounds__(NT, 2) __cluster_dims__(2, 1, 1)
void region_score_dsplit(const float* __restrict__ ftrain,
                         const float* __restrict__ ftest,
                         const int*   __restrict__ Kp,
                         float* __restrict__ out,
                         int halfOut)
{
    extern __shared__ float sm[];
    float* tT  = sm + T_OFF;
    float* tR  = sm + R_OFF;
    float* parT= sm + PAR_T;
    float* parR= sm + PAR_R;
    float* mT  = sm + MEAN_T;
    float* mR  = sm + MEAN_R;
    float* X   = sm + X_OFF;
    float* I1  = sm + INB1;
    float* nrm = sm + NRM;
    float* scr = sm + SCR;
    float* ww  = sm + WWT;
    float* red = sm + RED;
    float* myD = sm + X2_OFF;
    float* I2  = sm + INB2;
    float* ubuf= parT;               // reuse after means

    const int g    = blockIdx.x >> 1;
    const int role = blockIdx.x & 1;
    const int tid  = threadIdx.x;
    const int lane = tid & 31;
    const int wid  = tid >> 5;
    const int K    = Kp[0];
    const uint32_t peer  = (uint32_t)(role ^ 1);
    const uint32_t sbase = smem_u32(sm);

    // break symmetric lockstep between the two co-resident placement layers
    if (((unsigned)blockIdx.x / 148u) & 1u) __nanosleep(1500);

    // ---------------- load own d-half of both tensors (coalesced) ----------
    {
        const float4* gt = (const float4*)ftest  + (size_t)g * 4608 + role * 2304;
        const float4* gr = (const float4*)ftrain + (size_t)g * 4608 + role * 2304;
#pragma unroll
        for (int k = 0; k < 4; k++) {
            int j = tid + k * NT;            // 0..2047
            float4 a = gt[j];
            float4 b = gr[j];
            int d = j / 9;
            int p = (j - d * 9) * 4;
            int s = d * PS + p;
            tT[s]=a.x; tT[s+1]=a.y; tT[s+2]=a.z; tT[s+3]=a.w;
            tR[s]=b.x; tR[s+1]=b.y; tR[s+2]=b.z; tR[s+3]=b.w;
            parT[j] = a.x + a.y + a.z + a.w;
            parR[j] = b.x + b.y + b.z + b.w;
        }
        if (tid < 2304 - 4 * NT) {           // tail 256 jobs
            int j = tid + 4 * NT;
            float4 a = gt[j];
            float4 b = gr[j];
            int d = j / 9;
            int p = (j - d * 9) * 4;
            int s = d * PS + p;
            tT[s]=a.x; tT[s+1]=a.y; tT[s+2]=a.z; tT[s+3]=a.w;
            tR[s]=b.x; tR[s+1]=b.y; tR[s+2]=b.z; tR[s+3]=b.w;
            parT[j] = a.x + a.y + a.z + a.w;
            parR[j] = b.x + b.y + b.z + b.w;
        }
    }
    __syncthreads();                         // s1: tiles + partials

    // ---------------- means: local per-d (rows are entirely local) ---------
    if (tid < DH) {
        float s = 0.f;
#pragma unroll
        for (int k = 0; k < 9; k++) s += parT[9 * tid + k];
        mT[tid] = s * (1.0f / PP);
    } else {
        int t = tid - DH;
        float s = 0.f;
#pragma unroll
        for (int k = 0; k < 9; k++) s += parR[9 * t + k];
        mR[t] = s * (1.0f / PP);
    }
    __syncthreads();                         // s2: means

    // ---------------- stage A partials (warps 0-7) + stage B (all) ---------
    if (tid < DH) {
        float mt = mT[tid], mr = mR[tid];
        float a = warp_sum(mt * mr);
        float b = warp_sum(mt * mt);
        float c = warp_sum(mr * mr);
        if (lane == 0) { red[wid] = a; red[8 + wid] = b; red[16 + wid] = c; }
    }
    {
        float mtc[8], mrc[8];
#pragma unroll
        for (int i = 0; i < 8; i++) { mtc[i] = mT[lane + 32*i]; mrc[i] = mR[lane + 32*i]; }
#pragma unroll
        for (int rr = 0; rr < 5; rr++) {
            if (rr == 4 && wid >= 8) break;
            const int j    = wid + 16 * rr;          // 0..71
            const int tens = (j >= PP) ? 1 : 0;
            const int p    = j - PP * tens;
            const float* Xt = tens ? tR : tT;
            float a2 = 0.f, ta = 0.f;
#pragma unroll
            for (int i = 0; i < 8; i++) {
                float x = Xt[(lane + 32*i) * PS + p];
                a2 += x * x;
                ta += x * (tens ? mtc[i] : mrc[i]);  // vs OTHER tensor's mean
            }
            a2 = warp_sum(a2);
            ta = warp_sum(ta);
            if (lane == 0) { X[3 + j] = a2; X[75 + j] = ta; }
        }
    }
    __syncthreads();                         // s3: red + X partials ready

    // ---------------- fold stage A, exchange partials, merge ----------------
    if (tid < 3) {
        float s = 0.f;
#pragma unroll
        for (int i = 0; i < 8; i++) s += red[8 * tid + i];
        X[tid] = s;
        st_cluster_f32(sbase + (X_OFF - X_OFF + INB1 + tid) * 4u, peer, s);
    } else if (tid < 147) {
        st_cluster_f32(sbase + (INB1 + tid) * 4u, peer, X[tid]);
    }
    CLUSTER_SYNC();                          // peer partials in I1

    if (tid < 72) {
        float n2 = X[3 + tid]  + I1[3 + tid];
        float ta = X[75 + tid] + I1[75 + tid];
        float n  = fmaxf(sqrtf(fmaxf(n2, 0.f)), EPSN);
        nrm[tid] = n;
        scr[tid] = ta / n;                   // positive factors cancel in ranking
    }
    if (role == 0 && tid == 0) {
        float mm  = X[0] + I1[0];
        float mt2 = X[1] + I1[1];
        float mr2 = X[2] + I1[2];
        float den = fmaxf(sqrtf(mt2), EPSN) * fmaxf(sqrtf(mr2), EPSN);
        out[g] = SCALE_CLS * mm / den;
    }
    __syncthreads();                         // s4: scores/norms merged

    // ---------------- stage C: top-K rank counting (both CTAs, identical) ---
    if (tid < 72) {
        const int tens = (tid >= PP) ? 1 : 0;
        const int p    = tid - PP * tens;
        const int b0   = PP * tens;
        const float sv = scr[tid];
        int rank = 0;
#pragma unroll
        for (int q = 0; q < PP; q++) {
            float o = scr[b0 + q];
            rank += (o > sv) || (o == sv && q < p);  // lower index wins ties
        }
        ww[tid] = (rank < K) ? (1.0f / nrm[tid]) : 0.0f;
    }
    __syncthreads();                         // s5: weights

    // ---------------- stage D: fused half-vectors ---------------------------
    {
        const int th  = tid >> 8;            // 0 test, 1 train
        const int row = tid & 255;
        const float* tile = th ? tR : tT;
        const float* w = ww + th * PP;
        const float* rr_ = tile + row * PS;
        float u = 0.f;
#pragma unroll
        for (int p = 0; p < PP; p++) u += rr_[p] * w[p];   // w reads broadcast
        ubuf[tid] = u;
    }
    __syncthreads();                         // s6: ubuf

    if (tid < DH) {
        float ut = ubuf[tid];
        float vt = ubuf[DH + tid];
        float a = warp_sum(ut * vt);
        float b = warp_sum(ut * ut);
        float c = warp_sum(vt * vt);
        if (lane == 0) { red[wid] = a; red[8 + wid] = b; red[16 + wid] = c; }
    }
    __syncthreads();                         // s7: red

    if (tid < 3) {
        float s = 0.f;
#pragma unroll
        for (int i = 0; i < 8; i++) s += red[8 * tid + i];
        myD[tid] = s;
        st_cluster_f32(sbase + (INB2 + tid) * 4u, peer, s);
    }
    CLUSTER_SYNC();                          // peer stage-D partials in I2

    if (role == 0 && tid == 0) {
        float uv = myD[0] + I2[0];
        float uu = myD[1] + I2[1];
        float vv = myD[2] + I2[2];
        float den = fmaxf(sqrtf(fmaxf(uu, 0.f)), EPSN) * fmaxf(sqrtf(fmaxf(vv, 0.f)), EPSN);
        out[halfOut + g] = SCALE_CLS * uv / den;
    }
}

extern "C" void kernel_launch(void* const* d_in, const int* in_sizes, int n_in,
                              void* d_out, int out_size)
{
    const float* ftrain = (const float*)d_in[0];
    const float* ftest  = (const float*)d_in[1];
    const int*   Kp     = (const int*)d_in[2];
    float* out = (float*)d_out;

    const int groups  = in_sizes[0] / (DD * PP);   // 1500
    const int halfOut = out_size / 2;              // 1500

    cudaFuncSetAttribute(region_score_dsplit,
                         cudaFuncAttributeMaxDynamicSharedMemorySize, SMEMB);
    region_score_dsplit<<<groups * 2, NT, SMEMB>>>(ftrain, ftest, Kp, out, halfOut);
}

// round 14
// speedup vs baseline: 1.0004x; 1.0004x over previous
#include <cuda_runtime.h>
#include <math.h>
#include <stdint.h>

#define DD 512
#define PP 36
#define PS 37                        // padded row stride: conflict-free everywhere
#define NT 512
#define EPSN 1e-12f
#define SCALE_CLS 7.0f
#define TILE_F (DD*PP)               // 18432 floats per gmem tile

// SMEM float offsets
#define TILE_T  0                    // test tile  [512][37]
#define TILE_R  18944                // train tile [512][37]
#define STAGE   37888                // dense train staging [18432]
#define MT_OFF  56320                // mean test  [512]
#define MR_OFF  56832                // mean train [512]
#define NT_OFF  57344                // norms test [40]
#define NR_OFF  57384
#define STE_OFF 57424                // sel scores test [40]
#define STR_OFF 57464
#define WT_OFF  57504                // fuse weights [40]
#define WR_OFF  57544
#define RED_OFF 57584                // reduction scratch [48]
#define SMEMF   57632
#define SMEMB   (SMEMF*4)            // 230,528 B

__device__ __forceinline__ float warp_sum(float v) {
#pragma unroll
    for (int o = 16; o > 0; o >>= 1) v += __shfl_down_sync(0xffffffffu, v, o);
    return v;
}

__device__ __forceinline__ void cp_async16(uint32_t saddr, const void* g) {
    asm volatile("cp.async.cg.shared.global [%0], [%1], 16;" :: "r"(saddr), "l"(g));
}
#define CP_COMMIT() asm volatile("cp.async.commit_group;" ::: "memory")
#define CP_WAIT0()  asm volatile("cp.async.wait_group 0;"  ::: "memory")

__global__ __launch_bounds__(NT, 1)
void fused_region_score_v3(const float* __restrict__ ftrain,
                           const float* __restrict__ ftest,
                           const int*   __restrict__ Kp,
                           float* __restrict__ out,
                           int groups, int halfOut)
{
    extern __shared__ float sm[];
    float* tT   = sm + TILE_T;
    float* tR   = sm + TILE_R;
    float* stg  = sm + STAGE;
    float* mean_t = sm + MT_OFF;
    float* mean_r = sm + MR_OFF;
    float* nt   = sm + NT_OFF;
    float* nr   = sm + NR_OFF;
    float* s_te = sm + STE_OFF;
    float* s_tr = sm + STR_OFF;
    float* wt   = sm + WT_OFF;
    float* wr   = sm + WR_OFF;
    float* red  = sm + RED_OFF;

    const int tid  = threadIdx.x;
    const int lane = tid & 31;
    const int wid  = tid >> 5;
    const int K    = Kp[0];

    const uint32_t stgA = (uint32_t)__cvta_generic_to_shared(stg);

    // contiguous group range per CTA
    const int nc = gridDim.x;
    const int q  = groups / nc, r = groups % nc;
    const int gbeg = blockIdx.x * q + min(blockIdx.x, r);
    const int gend = gbeg + q + (blockIdx.x < r ? 1 : 0);
    if (gbeg >= gend) return;

    // ---- prologue: stage train(gbeg) asynchronously -------------------------
    {
        const float4* src = (const float4*)(ftrain + (size_t)gbeg * TILE_F);
#pragma unroll
        for (int k = 0; k < 9; k++) {
            int j = tid + k * NT;
            cp_async16(stgA + (uint32_t)j * 16u, src + j);
        }
        CP_COMMIT();
    }

    for (int g = gbeg; g < gend; g++) {
        // ---- step 1: load test(g) direct LDG -> padded tile -----------------
        {
            const float4* gt = (const float4*)(ftest + (size_t)g * TILE_F);
#pragma unroll
            for (int k = 0; k < 9; k++) {
                int j = tid + k * NT;            // 0..4607, coalesced
                float4 a = gt[j];
                int d = j / 9;
                int p = (j - d * 9) * 4;
                int s = d * PS + p;
                tT[s] = a.x; tT[s+1] = a.y; tT[s+2] = a.z; tT[s+3] = a.w;
            }
        }
        CP_WAIT0();                              // train(g) staged
        __syncthreads();                         // s1: tileT + stage visible

        // ---- step 2: transpose train stage -> padded tile --------------------
        {
            const float4* s4 = (const float4*)stg;
#pragma unroll
            for (int k = 0; k < 9; k++) {
                int j = tid + k * NT;
                float4 a = s4[j];
                int d = j / 9;
                int p = (j - d * 9) * 4;
                int s = d * PS + p;
                tR[s] = a.x; tR[s+1] = a.y; tR[s+2] = a.z; tR[s+3] = a.w;
            }
        }
        __syncthreads();                         // s2: tileR ready, stage free

        // ---- step 3: prefetch train(g+1) into stage (async, hidden) ---------
        if (g + 1 < gend) {
            const float4* src = (const float4*)(ftrain + (size_t)(g + 1) * TILE_F);
#pragma unroll
            for (int k = 0; k < 9; k++) {
                int j = tid + k * NT;
                cp_async16(stgA + (uint32_t)j * 16u, src + j);
            }
            CP_COMMIT();
        }

        // ---- step 4: means (row reads) + fused stage-A partials -------------
        {
            const int d = tid;
            const float* rt = tT + d * PS;
            const float* rr = tR + d * PS;
            float sa = 0.f, sb = 0.f;
#pragma unroll
            for (int p = 0; p < PP; p++) { sa += rt[p]; sb += rr[p]; }
            float mt = sa * (1.0f / PP);
            float mr = sb * (1.0f / PP);
            mean_t[d] = mt;
            mean_r[d] = mr;
            float mm  = warp_sum(mt * mr);
            float mt2 = warp_sum(mt * mt);
            float mr2 = warp_sum(mr * mr);
            if (lane == 0) { red[wid] = mm; red[16 + wid] = mt2; red[32 + wid] = mr2; }
        }
        __syncthreads();                         // s3: means + redA ready

        // ---- step 5: stage B, register-cached means --------------------------
        {
            float mtc[16], mrc[16];
#pragma unroll
            for (int i = 0; i < 16; i++) {
                mtc[i] = mean_t[lane + 32 * i];
                mrc[i] = mean_r[lane + 32 * i];
            }
#pragma unroll
            for (int rr = 0; rr < 3; rr++) {
                if (rr == 2 && wid >= 4) break;
                const int p = wid + 16 * rr;     // 0..35
                float a2 = 0.f, b2 = 0.f, ta = 0.f, tb = 0.f;
#pragma unroll
                for (int i = 0; i < 16; i++) {
                    int d = lane + 32 * i;
                    float a = tT[d * PS + p];
                    float b = tR[d * PS + p];
                    a2 += a * a;
                    b2 += b * b;
                    ta += a * mrc[i];            // test vs mean_train
                    tb += b * mtc[i];            // train vs mean_test
                }
                a2 = warp_sum(a2); b2 = warp_sum(b2);
                ta = warp_sum(ta); tb = warp_sum(tb);
                if (lane == 0) {
                    float na = fmaxf(sqrtf(a2), EPSN);
                    float nb = fmaxf(sqrtf(b2), EPSN);
                    nt[p] = na;  s_te[p] = ta / na;   // positive factors cancel in ranking
                    nr[p] = nb;  s_tr[p] = tb / nb;
                }
            }
        }
        __syncthreads();                         // s4: scores/norms ready

        // ---- step 6: stage A final + stage C (same barrier section) ----------
        if (wid == 0) {
            float a = (lane < 16) ? red[lane]      : 0.f;
            float b = (lane < 16) ? red[16 + lane] : 0.f;
            float c = (lane < 16) ? red[32 + lane] : 0.f;
            a = warp_sum(a); b = warp_sum(b); c = warp_sum(c);
            if (lane == 0) {
                float den = fmaxf(sqrtf(b), EPSN) * fmaxf(sqrtf(c), EPSN);
                out[g] = SCALE_CLS * a / den;
            }
        }
        if (tid >= 64 && tid < 64 + PP) {        // test top-K
            const int p = tid - 64;
            const float sv = s_te[p];
            int rank = 0;
#pragma unroll
            for (int qq = 0; qq < PP; qq++) {
                float o = s_te[qq];
                rank += (o > sv) || (o == sv && qq < p);   // lower index wins ties
            }
            wt[p] = (rank < K) ? (1.0f / nt[p]) : 0.0f;
        }
        if (tid >= 128 && tid < 128 + PP) {      // train top-K
            const int p = tid - 128;
            const float sv = s_tr[p];
            int rank = 0;
#pragma unroll
            for (int qq = 0; qq < PP; qq++) {
                float o = s_tr[qq];
                rank += (o > sv) || (o == sv && qq < p);
            }
            wr[p] = (rank < K) ? (1.0f / nr[p]) : 0.0f;
        }
        __syncthreads();                         // s5: weights ready

        // ---- step 7: stage D + final score ------------------------------------
        {
            const int d = tid;
            const float* rt = tT + d * PS;
            const float* rr = tR + d * PS;
            float u = 0.f, v = 0.f;
#pragma unroll
            for (int p = 0; p < PP; p++) {
                u += rt[p] * wt[p];              // weight reads broadcast
                v += rr[p] * wr[p];
            }
            float uv = warp_sum(u * v);
            float uu = warp_sum(u * u);
            float vv = warp_sum(v * v);
            if (lane == 0) { red[wid] = uv; red[16 + wid] = uu; red[32 + wid] = vv; }
        }
        __syncthreads();                         // s6: redD ready

        if (wid == 0) {
            float a = (lane < 16) ? red[lane]      : 0.f;
            float b = (lane < 16) ? red[16 + lane] : 0.f;
            float c = (lane < 16) ? red[32 + lane] : 0.f;
            a = warp_sum(a); b = warp_sum(b); c = warp_sum(c);
            if (lane == 0) {
                float den = fmaxf(sqrtf(b), EPSN) * fmaxf(sqrtf(c), EPSN);
                out[halfOut + g] = SCALE_CLS * a / den;
            }
        }
        __syncthreads();                         // s7: tiles/red safe for next g
    }
}

extern "C" void kernel_launch(void* const* d_in, const int* in_sizes, int n_in,
                              void* d_out, int out_size)
{
    const float* ftrain = (const float*)d_in[0];
    const float* ftest  = (const float*)d_in[1];
    const int*   Kp     = (const int*)d_in[2];
    float* out = (float*)d_out;

    const int groups  = in_sizes[0] / (DD * PP);   // 1500
    const int halfOut = out_size / 2;              // 1500

    cudaFuncSetAttribute(fused_region_score_v3,
                         cudaFuncAttributeMaxDynamicSharedMemorySize, SMEMB);
    fused_region_score_v3<<<148, NT, SMEMB>>>(ftrain, ftest, Kp, out,
                                              groups, halfOut);
}

// round 15
// speedup vs baseline: 1.0743x; 1.0739x over previous
#include <cuda_runtime.h>
#include <math.h>

#define DD 512
#define PP 36
#define PS 37          // padded SMEM row stride: conflict-free row & column access
#define NTHREADS 512
#define EPSN 1e-12f
#define SCALE_CLS 7.0f
#define TILE_F (DD*PP)               // 18432 floats per tile
#define NJ (TILE_F/4)                // 4608 float4 jobs per tile

// SMEM layout (floats)
#define ST_OFF     0                 // test tile  [512][37]
#define SR_OFF     (DD*PS)           // train tile [512][37]
#define PT_OFF     (2*DD*PS)         // partial sums test  [4608]
#define PR_OFF     (PT_OFF + NJ)     // partial sums train [4608]
#define MT_OFF     (PR_OFF + NJ)     // mean test  [512]
#define MR_OFF     (MT_OFF + DD)     // mean train [512]
#define NT_OFF     (MR_OFF + DD)     // norms test [40]
#define NR_OFF     (NT_OFF + 40)
#define STE_OFF    (NR_OFF + 40)     // sel scores test [40]
#define STR_OFF    (STE_OFF + 40)
#define WT_OFF     (STR_OFF + 40)    // fuse weights [40]
#define WR_OFF     (WT_OFF + 40)
#define RED_OFF    (WR_OFF + 40)     // reduction scratch [48]
#define SMEM_FLOATS (RED_OFF + 48)
#define SMEM_BYTES  (SMEM_FLOATS * 4)   // ~194 KB

__device__ int g_ctr;

__device__ __forceinline__ float warp_sum(float v) {
#pragma unroll
    for (int o = 16; o > 0; o >>= 1) v += __shfl_down_sync(0xffffffffu, v, o);
    return v;
}

__global__ void reset_ctr() { g_ctr = 0; }

__global__ __launch_bounds__(NTHREADS, 1)
void fused_region_score_v4(const float* __restrict__ ftrain,
                           const float* __restrict__ ftest,
                           const int*   __restrict__ Kp,
                           float* __restrict__ out,
                           int groups, int halfOut)
{
    extern __shared__ float sm[];
    float* st     = sm + ST_OFF;
    float* sr     = sm + SR_OFF;
    float* pt     = sm + PT_OFF;
    float* pr     = sm + PR_OFF;
    float* mean_t = sm + MT_OFF;
    float* mean_r = sm + MR_OFF;
    float* nt     = sm + NT_OFF;
    float* nr     = sm + NR_OFF;
    float* s_te   = sm + STE_OFF;
    float* s_tr   = sm + STR_OFF;
    float* wt     = sm + WT_OFF;
    float* wr     = sm + WR_OFF;
    float* red    = sm + RED_OFF;
    __shared__ int s_g;

    const int tid  = threadIdx.x;
    const int lane = tid & 31;
    const int wid  = tid >> 5;
    const int K    = Kp[0];

    for (;;) {
        if (tid == 0) s_g = atomicAdd(&g_ctr, 1);
        __syncthreads();                       // s0: s_g valid (also WAR guard)
        const int g = s_g;
        if (g >= groups) break;

        // ---------------- load tiles + per-float4 partial sums -------------
        {
            const float4* gt = (const float4*)(ftest  + (size_t)g * TILE_F);
            const float4* gr = (const float4*)(ftrain + (size_t)g * TILE_F);
#pragma unroll
            for (int k = 0; k < 9; k++) {
                int j = tid + k * NTHREADS;    // 0..4607, coalesced
                float4 a = gt[j];
                float4 b = gr[j];
                int d = j / 9;
                int p = (j - d * 9) * 4;
                int s = d * PS + p;
                st[s] = a.x; st[s+1] = a.y; st[s+2] = a.z; st[s+3] = a.w;
                sr[s] = b.x; sr[s+1] = b.y; sr[s+2] = b.z; sr[s+3] = b.w;
                pt[j] = a.x + a.y + a.z + a.w;
                pr[j] = b.x + b.y + b.z + b.w;
            }
        }
        __syncthreads();                       // s1: tiles + partials ready

        // ---------------- means + stage-A partials --------------------------
        {
            const int d = tid;
            float sa = 0.f, sb = 0.f;
#pragma unroll
            for (int k = 0; k < 9; k++) { sa += pt[9*d + k]; sb += pr[9*d + k]; }
            float mt = sa * (1.0f / PP);
            float mr = sb * (1.0f / PP);
            mean_t[d] = mt;
            mean_r[d] = mr;
            float mm  = warp_sum(mt * mr);
            float mt2 = warp_sum(mt * mt);
            float mr2 = warp_sum(mr * mr);
            if (lane == 0) { red[wid] = mm; red[16 + wid] = mt2; red[32 + wid] = mr2; }
        }
        __syncthreads();                       // s2: means + redA ready

        // ---------------- stage B: paired jobs, register-cached means -------
        {
            float mtc[16], mrc[16];
#pragma unroll
            for (int i = 0; i < 16; i++) {
                mtc[i] = mean_t[lane + 32 * i];
                mrc[i] = mean_r[lane + 32 * i];
            }
            // round 1: jobs p0 = wid and p1 = wid+16, interleaved
            {
                const int p0 = wid, p1 = wid + 16;
                float a20=0.f, b20=0.f, ta0=0.f, tb0=0.f;
                float a21=0.f, b21=0.f, ta1=0.f, tb1=0.f;
#pragma unroll
                for (int i = 0; i < 16; i++) {
                    int d = lane + 32 * i;
                    const float* rt = st + d * PS;
                    const float* rr = sr + d * PS;
                    float aT0 = rt[p0], aT1 = rt[p1];
                    float aR0 = rr[p0], aR1 = rr[p1];
                    a20 += aT0 * aT0;  ta0 += aT0 * mrc[i];
                    b20 += aR0 * aR0;  tb0 += aR0 * mtc[i];
                    a21 += aT1 * aT1;  ta1 += aT1 * mrc[i];
                    b21 += aR1 * aR1;  tb1 += aR1 * mtc[i];
                }
                a20 = warp_sum(a20); b20 = warp_sum(b20);
                ta0 = warp_sum(ta0); tb0 = warp_sum(tb0);
                a21 = warp_sum(a21); b21 = warp_sum(b21);
                ta1 = warp_sum(ta1); tb1 = warp_sum(tb1);
                if (lane == 0) {
                    float na0 = fmaxf(sqrtf(a20), EPSN);
                    float nb0 = fmaxf(sqrtf(b20), EPSN);
                    nt[p0] = na0;  s_te[p0] = ta0 / na0;
                    nr[p0] = nb0;  s_tr[p0] = tb0 / nb0;
                    float na1 = fmaxf(sqrtf(a21), EPSN);
                    float nb1 = fmaxf(sqrtf(b21), EPSN);
                    nt[p1] = na1;  s_te[p1] = ta1 / na1;
                    nr[p1] = nb1;  s_tr[p1] = tb1 / nb1;
                }
            }
            // round 2: jobs 32..35 on warps 0..3
            if (wid < 4) {
                const int p = wid + 32;
                float a2=0.f, b2=0.f, ta=0.f, tb=0.f;
#pragma unroll
                for (int i = 0; i < 16; i++) {
                    int d = lane + 32 * i;
                    float a = st[d * PS + p];
                    float b = sr[d * PS + p];
                    a2 += a * a;  ta += a * mrc[i];
                    b2 += b * b;  tb += b * mtc[i];
                }
                a2 = warp_sum(a2); b2 = warp_sum(b2);
                ta = warp_sum(ta); tb = warp_sum(tb);
                if (lane == 0) {
                    float na = fmaxf(sqrtf(a2), EPSN);
                    float nb = fmaxf(sqrtf(b2), EPSN);
                    nt[p] = na;  s_te[p] = ta / na;
                    nr[p] = nb;  s_tr[p] = tb / nb;
                }
            }
        }
        __syncthreads();                       // s3: scores/norms ready

        // ---------------- stage A final + stage C ---------------------------
        if (wid == 0) {
            float a = (lane < 16) ? red[lane]      : 0.f;
            float b = (lane < 16) ? red[16 + lane] : 0.f;
            float c = (lane < 16) ? red[32 + lane] : 0.f;
            a = warp_sum(a); b = warp_sum(b); c = warp_sum(c);
            if (lane == 0) {
                float den = fmaxf(sqrtf(b), EPSN) * fmaxf(sqrtf(c), EPSN);
                out[g] = SCALE_CLS * a / den;
            }
        }
        if (tid >= 64 && tid < 64 + PP) {      // test top-K
            const int p = tid - 64;
            const float sv = s_te[p];
            int rank = 0;
#pragma unroll
            for (int q = 0; q < PP; q++) {
                float o = s_te[q];
                rank += (o > sv) || (o == sv && q < p);   // lower index wins ties
            }
            wt[p] = (rank < K) ? (1.0f / nt[p]) : 0.0f;
        }
        if (tid >= 128 && tid < 128 + PP) {    // train top-K
            const int p = tid - 128;
            const float sv = s_tr[p];
            int rank = 0;
#pragma unroll
            for (int q = 0; q < PP; q++) {
                float o = s_tr[q];
                rank += (o > sv) || (o == sv && q < p);
            }
            wr[p] = (rank < K) ? (1.0f / nr[p]) : 0.0f;
        }
        __syncthreads();                       // s4: weights ready

        // ---------------- stage D: fused features + final score -------------
        {
            const int d = tid;
            const float* rt = st + d * PS;
            const float* rr = sr + d * PS;
            float u = 0.f, v = 0.f;
#pragma unroll
            for (int p = 0; p < PP; p++) {
                u += rt[p] * wt[p];            // weight reads broadcast
                v += rr[p] * wr[p];
            }
            float uv = warp_sum(u * v);
            float uu = warp_sum(u * u);
            float vv = warp_sum(v * v);
            if (lane == 0) { red[wid] = uv; red[16 + wid] = uu; red[32 + wid] = vv; }
        }
        __syncthreads();                       // s5: redD ready

        if (wid == 0) {
            float a = (lane < 16) ? red[lane]      : 0.f;
            float b = (lane < 16) ? red[16 + lane] : 0.f;
            float c = (lane < 16) ? red[32 + lane] : 0.f;
            a = warp_sum(a); b = warp_sum(b); c = warp_sum(c);
            if (lane == 0) {
                float den = fmaxf(sqrtf(b), EPSN) * fmaxf(sqrtf(c), EPSN);
                out[halfOut + g] = SCALE_CLS * a / den;
            }
        }
        // next iteration's s0 barrier protects red/tiles reuse
    }
}

extern "C" void kernel_launch(void* const* d_in, const int* in_sizes, int n_in,
                              void* d_out, int out_size)
{
    const float* ftrain = (const float*)d_in[0];
    const float* ftest  = (const float*)d_in[1];
    const int*   Kp     = (const int*)d_in[2];
    float* out = (float*)d_out;

    const int groups  = in_sizes[0] / (DD * PP);   // 1500
    const int halfOut = out_size / 2;              // 1500

    reset_ctr<<<1, 1>>>();
    cudaFuncSetAttribute(fused_region_score_v4,
                         cudaFuncAttributeMaxDynamicSharedMemorySize, SMEM_BYTES);
    fused_region_score_v4<<<148, NTHREADS, SMEM_BYTES>>>(ftrain, ftest, Kp,
                                                         out, groups, halfOut);
}

// round 16
// speedup vs baseline: 1.0823x; 1.0074x over previous
#include <cuda_runtime.h>
#include <math.h>

#define DD 512
#define PP 36
#define PS 37                        // padded row stride: conflict-free
#define NT 512
#define EPSN 1e-12f
#define SCALE_CLS 7.0f
#define TILE_F (DD*PP)               // 18432 floats per gmem tile

// SMEM layout (floats)
#define TOFF   0                     // kept tile [512][37]
#define PAR    (DD*PS)               // stream partials [4608] (reused per phase)
#define MEANT  (PAR + TILE_F/4)      // mean of phase-1 tensor (test) [512]
#define MEANR  (MEANT + DD)          // mean of phase-2 tensor (train) [512]
#define NNO    (MEANR + DD)          // own per-position norms [40]
#define SSO    (NNO + 40)            // own selection scores [40]
#define WWO    (SSO + 40)            // own fuse weights [40]
#define REDO   (WWO + 40)            // reduction scratch [48]
#define SMEMF  (REDO + 48)
#define SMEMB  (SMEMF * 4)           // ~99.0 KB -> 2 CTAs/SM

#define MAXG 4096
__device__ float g_fuse[MAXG * 2 * DD];   // fused vectors scratch (16 MB)

__device__ __forceinline__ float warp_sum(float v) {
#pragma unroll
    for (int o = 16; o > 0; o >>= 1) v += __shfl_down_sync(0xffffffffu, v, o);
    return v;
}

__global__ __launch_bounds__(NT, 2)
void region_score_half(const float* __restrict__ ftrain,
                       const float* __restrict__ ftest,
                       const int*   __restrict__ Kp,
                       float* __restrict__ out)
{
    extern __shared__ float sm[];
    float* tile  = sm + TOFF;
    float* par   = sm + PAR;
    float* meanT = sm + MEANT;
    float* meanR = sm + MEANR;
    float* nn    = sm + NNO;
    float* ss    = sm + SSO;
    float* ww    = sm + WWO;
    float* red   = sm + REDO;

    const int g    = blockIdx.x >> 1;
    const int side = blockIdx.x & 1;    // 0: keep test, 1: keep train
    const int tid  = threadIdx.x;
    const int lane = tid & 31;
    const int wid  = tid >> 5;
    const int K    = Kp[0];

    const float* t1 = ftest  + (size_t)g * TILE_F;   // phase-1 tensor
    const float* t2 = ftrain + (size_t)g * TILE_F;   // phase-2 tensor

    // ---------------- phase 1: test tensor --------------------------------
    if (side == 0) {
        const float4* s4 = (const float4*)t1;
#pragma unroll
        for (int k = 0; k < 9; k++) {
            int j = tid + k * NT;
            float4 a = s4[j];
            int d = j / 9;
            int p = (j - d * 9) * 4;
            int s = d * PS + p;
            tile[s] = a.x; tile[s+1] = a.y; tile[s+2] = a.z; tile[s+3] = a.w;
            par[j] = a.x + a.y + a.z + a.w;
        }
    } else {
        const float4* s4 = (const float4*)t1;
#pragma unroll
        for (int k = 0; k < 9; k++) {
            int j = tid + k * NT;
            float4 a = s4[j];
            par[j] = a.x + a.y + a.z + a.w;
        }
    }
    __syncthreads();                    // s1: partials ready
    {
        float s = 0.f;
#pragma unroll
        for (int k = 0; k < 9; k++) s += par[9 * tid + k];
        meanT[tid] = s * (1.0f / PP);
    }
    __syncthreads();                    // s2: meanT done, par reusable

    // ---------------- phase 2: train tensor -------------------------------
    if (side == 1) {
        const float4* s4 = (const float4*)t2;
#pragma unroll
        for (int k = 0; k < 9; k++) {
            int j = tid + k * NT;
            float4 a = s4[j];
            int d = j / 9;
            int p = (j - d * 9) * 4;
            int s = d * PS + p;
            tile[s] = a.x; tile[s+1] = a.y; tile[s+2] = a.z; tile[s+3] = a.w;
            par[j] = a.x + a.y + a.z + a.w;
        }
    } else {
        const float4* s4 = (const float4*)t2;
#pragma unroll
        for (int k = 0; k < 9; k++) {
            int j = tid + k * NT;
            float4 a = s4[j];
            par[j] = a.x + a.y + a.z + a.w;
        }
    }
    __syncthreads();                    // s3: partials ready
    {
        float s = 0.f;
#pragma unroll
        for (int k = 0; k < 9; k++) s += par[9 * tid + k];
        float mr = s * (1.0f / PP);
        meanR[tid] = mr;
        float mt = meanT[tid];
        float a = warp_sum(mt * mr);
        float b = warp_sum(mt * mt);
        float c = warp_sum(mr * mr);
        if (lane == 0) { red[wid] = a; red[16 + wid] = b; red[32 + wid] = c; }
    }
    __syncthreads();                    // s4: means + redA ready

    if (side == 0 && wid == 0) {
        float a = (lane < 16) ? red[lane]      : 0.f;
        float b = (lane < 16) ? red[16 + lane] : 0.f;
        float c = (lane < 16) ? red[32 + lane] : 0.f;
        a = warp_sum(a); b = warp_sum(b); c = warp_sum(c);
        if (lane == 0) {
            float den = fmaxf(sqrtf(b), EPSN) * fmaxf(sqrtf(c), EPSN);
            out[g] = SCALE_CLS * a / den;
        }
    }

    // ---------------- stage B (own side): norms + selection scores ---------
    {
        const float* M = side ? meanT : meanR;   // other tensor's mean
        float mc[16];
#pragma unroll
        for (int i = 0; i < 16; i++) mc[i] = M[lane + 32 * i];
#pragma unroll
        for (int rr = 0; rr < 3; rr++) {
            if (rr == 2 && wid >= 4) break;
            const int p = wid + 16 * rr;         // 0..35
            float a2 = 0.f, ta = 0.f;
#pragma unroll
            for (int i = 0; i < 16; i++) {
                float x = tile[(lane + 32 * i) * PS + p];
                a2 += x * x;
                ta += x * mc[i];
            }
            a2 = warp_sum(a2);
            ta = warp_sum(ta);
            if (lane == 0) {
                float n = fmaxf(sqrtf(a2), EPSN);
                nn[p] = n;
                ss[p] = ta / n;   // positive constant factors cancel in ranking
            }
        }
    }
    __syncthreads();                    // s5: scores/norms ready

    // ---------------- stage C: top-K via rank counting ---------------------
    if (tid < PP) {
        const float sv = ss[tid];
        int rank = 0;
#pragma unroll
        for (int q = 0; q < PP; q++) {
            float o = ss[q];
            rank += (o > sv) || (o == sv && q < tid);   // lower index wins ties
        }
        ww[tid] = (rank < K) ? (1.0f / nn[tid]) : 0.0f;
    }
    __syncthreads();                    // s6: weights ready

    // ---------------- stage D: fused vector -> global scratch --------------
    {
        const float* row = tile + tid * PS;
        float u = 0.f;
#pragma unroll
        for (int p = 0; p < PP; p++) u += row[p] * ww[p];   // ww reads broadcast
        g_fuse[((size_t)g * 2 + side) * DD + tid] = u;
    }
}

// one WARP per group: single-wave finalize
__global__ __launch_bounds__(NT, 2)
void region_score_final2(float* __restrict__ out, int groups, int halfOut)
{
    const int gw   = blockIdx.x * (NT / 32) + (threadIdx.x >> 5);
    const int lane = threadIdx.x & 31;
    if (gw >= groups) return;

    const float4* U = (const float4*)(g_fuse + (size_t)gw * 2 * DD);
    const float4* V = U + DD / 4;
    float uv = 0.f, uu = 0.f, vv = 0.f;
#pragma unroll
    for (int i = 0; i < 4; i++) {
        float4 u = U[lane + 32 * i];
        float4 v = V[lane + 32 * i];
        uv += u.x*v.x + u.y*v.y + u.z*v.z + u.w*v.w;
        uu += u.x*u.x + u.y*u.y + u.z*u.z + u.w*u.w;
        vv += v.x*v.x + v.y*v.y + v.z*v.z + v.w*v.w;
    }
    uv = warp_sum(uv);
    uu = warp_sum(uu);
    vv = warp_sum(vv);
    if (lane == 0) {
        float den = fmaxf(sqrtf(uu), EPSN) * fmaxf(sqrtf(vv), EPSN);
        out[halfOut + gw] = SCALE_CLS * uv / den;
    }
}

extern "C" void kernel_launch(void* const* d_in, const int* in_sizes, int n_in,
                              void* d_out, int out_size)
{
    const float* ftrain = (const float*)d_in[0];
    const float* ftest  = (const float*)d_in[1];
    const int*   Kp     = (const int*)d_in[2];
    float* out = (float*)d_out;

    const int groups  = in_sizes[0] / (DD * PP);   // 1500
    const int halfOut = out_size / 2;              // 1500

    cudaFuncSetAttribute(region_score_half,
                         cudaFuncAttributeMaxDynamicSharedMemorySize, SMEMB);
    region_score_half<<<groups * 2, NT, SMEMB>>>(ftrain, ftest, Kp, out);

    const int warpsPerCta = NT / 32;
    const int fgrid = (groups + warpsPerCta - 1) / warpsPerCta;   // 94
    region_score_final2<<<fgrid, NT>>>(out, groups, halfOut);
}